// round 7
// baseline (speedup 1.0000x reference)
#include <cuda_runtime.h>

#define NW 12
#define DIM 4096        // 2^12
#define INDIM 256
#define DEPTH 4
#define NT 256

// XOR swizzle so all three phase layouts are bank-conflict-free
__device__ __forceinline__ int slot(int i) { return i ^ ((i >> 4) & 0xF); }

// RX pair update: b0 = c*a0 - i s a1 ; b1 = -i s a0 + c*a1
__device__ __forceinline__ void rx_pair(float2& a0, float2& a1, float c, float s) {
    float b0x = fmaf(c, a0.x,  s * a1.y);
    float b0y = fmaf(c, a0.y, -s * a1.x);
    float b1x = fmaf(c, a1.x,  s * a0.y);
    float b1y = fmaf(c, a1.y, -s * a0.x);
    a0.x = b0x; a0.y = b0y; a1.x = b1x; a1.y = b1y;
}

// Apply RX butterflies on local bits [K0,4): local bit k acts on wire (wbase - k).
// Coefficients are read per-gate from shared memory (uniform broadcast) to keep
// register pressure low (5 CTAs/SM budget).
template<int K0>
__device__ __forceinline__ void applyK(float2 A[16], const float* __restrict__ pcd,
                                       const float* __restrict__ psd, int wbase) {
#pragma unroll
    for (int k = K0; k < 4; k++) {
        const float c = pcd[wbase - k];
        const float s = psd[wbase - k];
        const int m = 1 << k;
#pragma unroll
        for (int i0 = 0; i0 < 16; i0++)
            if (!(i0 & m)) rx_pair(A[i0], A[i0 | m], c, s);
    }
}

__global__ void __launch_bounds__(NT, 5)
sim_kernel(const float* __restrict__ x, const float* __restrict__ W,
           const float* __restrict__ params, float* __restrict__ out)
{
    __shared__ float2 st[DIM];              // 32 KB state
    __shared__ float ic[NW], isn[NW];       // merged initial-layer cos/sin (half-angle)
    __shared__ float pc[DEPTH * NW], ps[DEPTH * NW];   // d>=1 used
    __shared__ float red[NW * 8];
    __shared__ float2 plo[256];             // phase-folded product over bits 0..7
    __shared__ float2 phi[16];              // phase-folded product over bits 8..11
    __shared__ float osum[NW * 8];

    const int tid  = threadIdx.x;
    const int b    = blockIdx.x;
    const int lane = tid & 31;
    const int warp = tid >> 5;

    // ---- angles[b,w] = dot(x[b,:], W[w,:]) ----
    float xv = x[b * INDIM + tid];
#pragma unroll
    for (int w = 0; w < NW; w++) {
        float p = xv * __ldg(&W[w * INDIM + tid]);
#pragma unroll
        for (int o = 16; o > 0; o >>= 1) p += __shfl_xor_sync(0xffffffffu, p, o);
        if (lane == 0) red[w * 8 + warp] = p;
    }
    __syncthreads();
    if (tid < NW) {
        float a = 0.f;
#pragma unroll
        for (int k = 0; k < 8; k++) a += red[tid * 8 + k];
        // merge depth-0 RX into the initial layer (no CNOT between them);
        // wire 11 is target-only: its RX commutes through every chain -> merge all depths
        float th = a + params[tid];
        if (tid == 11) th += params[NW + 11] + params[2 * NW + 11] + params[3 * NW + 11];
        float sv, cv; sincosf(th * 0.5f, &sv, &cv);
        ic[tid] = cv; isn[tid] = sv;
    }
    if (tid < DEPTH * NW) {
        float sv, cv; sincosf(params[tid] * 0.5f, &sv, &cv);
        pc[tid] = cv; ps[tid] = sv;
    }
    __syncthreads();

    // ---- phase-folded product tables: amp(m) = phi[m>>8] * plo[m&255] (complex) ----
    {
        float v = 1.f;
#pragma unroll
        for (int bb = 0; bb < 8; bb++) v *= ((tid >> bb) & 1) ? isn[11 - bb] : ic[11 - bb];
        int c = __popc(tid) & 3;           // fold (-i)^popc(lo)
        float2 e;
        e.x = (c == 0) ? v : ((c == 2) ? -v : 0.f);
        e.y = (c == 1) ? -v : ((c == 3) ? v : 0.f);
        plo[tid] = e;
        if (tid < 16) {
            float u = 1.f;
#pragma unroll
            for (int bb = 0; bb < 4; bb++) u *= ((tid >> bb) & 1) ? isn[3 - bb] : ic[3 - bb];
            int ch = __popc(tid) & 3;      // fold (-i)^popc(hi)
            float2 eh;
            eh.x = (ch == 0) ? u : ((ch == 2) ? -u : 0.f);
            eh.y = (ch == 1) ? -u : ((ch == 3) ? u : 0.f);
            phi[tid] = eh;
        }
    }
    __syncthreads();

    // ---- construct state AFTER the first CNOT chain, directly in the depth-1
    //      hi layout: A[g] holds index j=(g<<8)|tid, value = amp(j ^ (j>>1))
    float2 A[16];
#pragma unroll
    for (int g = 0; g < 16; g++) {
        int j = (g << 8) | tid;
        int m = j ^ (j >> 1);
        float2 h = phi[m >> 8], l = plo[m & 255];
        float2 a;
        a.x = h.x * l.x - h.y * l.y;
        a.y = fmaf(h.x, l.y, h.y * l.x);
        A[g] = a;
    }

    const int mid_base = ((tid >> 4) << 8) | (tid & 15);

    // ---- depths 1..3: hi (wires 0-3), mid (wires 4-7), lo (wires 8-10; wire 11 merged out)
    for (int d = 1; d < DEPTH; d++) {
        const float* pcd = pc + d * NW;
        const float* psd = ps + d * NW;

        if (d > 1) {
            // hi-phase read with CNOT-chain perm fused: new[j] = old[j ^ (j>>1)]
#pragma unroll
            for (int g = 0; g < 16; g++) {
                int j = (g << 8) | tid;
                A[g] = st[slot(j ^ (j >> 1))];
            }
            __syncthreads();   // all perm reads before any write
        }
        applyK<0>(A, pcd, psd, 3);          // hi: local bit k <-> wire 3-k
#pragma unroll
        for (int g = 0; g < 16; g++) st[slot((g << 8) | tid)] = A[g];
        __syncthreads();

        // mid: local bit k <-> wire 7-k
#pragma unroll
        for (int g = 0; g < 16; g++) A[g] = st[slot(mid_base | (g << 4))];
        applyK<0>(A, pcd, psd, 7);
#pragma unroll
        for (int g = 0; g < 16; g++) st[slot(mid_base | (g << 4))] = A[g];
        __syncthreads();

        // lo: local bit k <-> wire 11-k ; k=0 (wire 11) already merged out
#pragma unroll
        for (int g = 0; g < 16; g++) A[g] = st[slot((tid << 4) | g)];
        applyK<1>(A, pcd, psd, 11);
        if (d < DEPTH - 1) {
#pragma unroll
            for (int g = 0; g < 16; g++) st[slot((tid << 4) | g)] = A[g];
            __syncthreads();
        }
        // d == DEPTH-1: amplitudes stay in registers for measurement
    }

    // ---- factorized per-wire measurement (final CNOT perm absorbed):
    // j = (tid<<4)|g.  Wires 0..7: sign depends only on tid -> +-psum.
    // Wires 8..11: sign = parity(popc(tid)) ^ parity(popc(g>>bb)) -> add/sub chains.
    float psum = 0.f, T3 = 0.f, T2 = 0.f, T1 = 0.f, T0 = 0.f;
#pragma unroll
    for (int g = 0; g < 16; g++) {
        const int g3 = (g >> 3) & 1, g2 = (g >> 2) & 1, g1 = (g >> 1) & 1, g0 = g & 1;
        float v = fmaf(A[g].x, A[g].x, A[g].y * A[g].y);
        psum += v;
        T3 += (g3) ? -v : v;                       // bb=3 (wire 8)
        T2 += (g3 ^ g2) ? -v : v;                  // bb=2 (wire 9)
        T1 += (g3 ^ g2 ^ g1) ? -v : v;             // bb=1 (wire 10)
        T0 += (g3 ^ g2 ^ g1 ^ g0) ? -v : v;        // bb=0 (wire 11)
    }

    // per-thread sign bits: wire w (0..7): parity(popc(tid >> (7-w)))
    int pm = 0;
    {
        int par = 0;
#pragma unroll
        for (int w = 0; w < 8; w++) { par ^= (tid >> (7 - w)) & 1; pm |= par << w; }
    }
    const int parT = __popc(tid) & 1;

    float vals[NW];
#pragma unroll
    for (int w = 0; w < 8; w++) vals[w] = ((pm >> w) & 1) ? -psum : psum;
    vals[8]  = parT ? -T3 : T3;
    vals[9]  = parT ? -T2 : T2;
    vals[10] = parT ? -T1 : T1;
    vals[11] = parT ? -T0 : T0;

#pragma unroll
    for (int w = 0; w < NW; w++) {
        float v = vals[w];
#pragma unroll
        for (int o = 16; o > 0; o >>= 1) v += __shfl_xor_sync(0xffffffffu, v, o);
        if (lane == 0) osum[w * 8 + warp] = v;
    }
    __syncthreads();
    if (tid < NW) {
        float t = 0.f;
#pragma unroll
        for (int k = 0; k < 8; k++) t += osum[tid * 8 + k];
        out[b * NW + tid] = t;
    }
}

extern "C" void kernel_launch(void* const* d_in, const int* in_sizes, int n_in,
                              void* d_out, int out_size)
{
    // Identify inputs by element count — robust to metadata ordering.
    const float* x = nullptr;      // 4096*256 = 1048576
    const float* W = nullptr;      // 12*256   = 3072
    const float* params = nullptr; // 4*12*1   = 48
    for (int i = 0; i < n_in; i++) {
        if      (in_sizes[i] == 4096 * 256) x      = (const float*)d_in[i];
        else if (in_sizes[i] == 12 * 256)   W      = (const float*)d_in[i];
        else if (in_sizes[i] == 48)         params = (const float*)d_in[i];
    }
    sim_kernel<<<4096, NT>>>(x, W, params, (float*)d_out);
}

// round 8
// speedup vs baseline: 1.1625x; 1.1625x over previous
#include <cuda_runtime.h>

#define NW 12
#define DIM 4096        // 2^12
#define INDIM 256
#define DEPTH 4
#define NT 256

// XOR swizzle so all three phase layouts are bank-conflict-free
__device__ __forceinline__ int slot(int i) { return i ^ ((i >> 4) & 0xF); }

// RX pair update: b0 = c*a0 - i s a1 ; b1 = -i s a0 + c*a1
__device__ __forceinline__ void rx_pair(float2& a0, float2& a1, float c, float s) {
    float b0x = fmaf(c, a0.x,  s * a1.y);
    float b0y = fmaf(c, a0.y, -s * a1.x);
    float b1x = fmaf(c, a1.x,  s * a0.y);
    float b1y = fmaf(c, a1.y, -s * a0.x);
    a0.x = b0x; a0.y = b0y; a1.x = b1x; a1.y = b1y;
}

// Apply RX butterflies on local bits [K0, 4) of A[16], register-resident coeffs
template<int K0>
__device__ __forceinline__ void applyK(float2 A[16], const float ck[4], const float sk[4]) {
#pragma unroll
    for (int k = K0; k < 4; k++) {
        const int m = 1 << k;
#pragma unroll
        for (int i0 = 0; i0 < 16; i0++)
            if (!(i0 & m)) rx_pair(A[i0], A[i0 | m], ck[k], sk[k]);
    }
}

__global__ void __launch_bounds__(NT, 4)
sim_kernel(const float* __restrict__ x, const float* __restrict__ W,
           const float* __restrict__ params, float* __restrict__ out)
{
    __shared__ float2 st[DIM];              // 32 KB state
    __shared__ float ic[NW], isn[NW];       // merged initial-layer cos/sin (half-angle)
    __shared__ float pc[DEPTH * NW], ps[DEPTH * NW];   // d>=1 used
    __shared__ float red[NW * 8];
    __shared__ float2 plo[256];             // phase-folded product over bits 0..7
    __shared__ float2 phi[16];              // phase-folded product over bits 8..11
    __shared__ float osum[NW * 8];

    const int tid  = threadIdx.x;
    const int b    = blockIdx.x;
    const int lane = tid & 31;
    const int warp = tid >> 5;

    // ---- angles[b,w] = dot(x[b,:], W[w,:]) ----
    float xv = x[b * INDIM + tid];
#pragma unroll
    for (int w = 0; w < NW; w++) {
        float p = xv * __ldg(&W[w * INDIM + tid]);
#pragma unroll
        for (int o = 16; o > 0; o >>= 1) p += __shfl_xor_sync(0xffffffffu, p, o);
        if (lane == 0) red[w * 8 + warp] = p;
    }
    __syncthreads();
    if (tid < NW) {
        float a = 0.f;
#pragma unroll
        for (int k = 0; k < 8; k++) a += red[tid * 8 + k];
        // merge depth-0 RX into the initial layer (no CNOT between them);
        // wire 11 is target-only: its RX commutes through every chain -> merge all depths
        float th = a + params[tid];
        if (tid == 11) th += params[NW + 11] + params[2 * NW + 11] + params[3 * NW + 11];
        float sv, cv; sincosf(th * 0.5f, &sv, &cv);
        ic[tid] = cv; isn[tid] = sv;
    }
    if (tid < DEPTH * NW) {
        float sv, cv; sincosf(params[tid] * 0.5f, &sv, &cv);
        pc[tid] = cv; ps[tid] = sv;
    }
    __syncthreads();

    // ---- phase-folded product tables: amp(m) = phi[m>>8] * plo[m&255] (complex) ----
    {
        float v = 1.f;
#pragma unroll
        for (int bb = 0; bb < 8; bb++) v *= ((tid >> bb) & 1) ? isn[11 - bb] : ic[11 - bb];
        int c = __popc(tid) & 3;           // fold (-i)^popc(lo)
        float2 e;
        e.x = (c == 0) ? v : ((c == 2) ? -v : 0.f);
        e.y = (c == 1) ? -v : ((c == 3) ? v : 0.f);
        plo[tid] = e;
        if (tid < 16) {
            float u = 1.f;
#pragma unroll
            for (int bb = 0; bb < 4; bb++) u *= ((tid >> bb) & 1) ? isn[3 - bb] : ic[3 - bb];
            int ch = __popc(tid) & 3;      // fold (-i)^popc(hi)
            float2 eh;
            eh.x = (ch == 0) ? u : ((ch == 2) ? -u : 0.f);
            eh.y = (ch == 1) ? -u : ((ch == 3) ? u : 0.f);
            phi[tid] = eh;
        }
    }
    __syncthreads();

    // ---- construct state AFTER the first CNOT chain, directly in the depth-1
    //      hi layout: A[g] holds index j=(g<<8)|tid, value = amp(j ^ (j>>1))
    float2 A[16];
#pragma unroll
    for (int g = 0; g < 16; g++) {
        int j = (g << 8) | tid;
        int m = j ^ (j >> 1);
        float2 h = phi[m >> 8], l = plo[m & 255];
        float2 a;
        a.x = h.x * l.x - h.y * l.y;
        a.y = fmaf(h.x, l.y, h.y * l.x);
        A[g] = a;
    }

    const int mid_base = ((tid >> 4) << 8) | (tid & 15);

    // ---- depths 1..3: hi (wires 0-3), mid (wires 4-7), lo (wires 8-10; wire 11 merged out)
    for (int d = 1; d < DEPTH; d++) {
        const float* pcd = pc + d * NW;
        const float* psd = ps + d * NW;

        if (d > 1) {
            // hi-phase read with CNOT-chain perm fused: new[j] = old[j ^ (j>>1)]
#pragma unroll
            for (int g = 0; g < 16; g++) {
                int j = (g << 8) | tid;
                A[g] = st[slot(j ^ (j >> 1))];
            }
            __syncthreads();   // all perm reads before any write
        }
        {   // hi: local bit k <-> wire 3-k
            float ck[4], sk[4];
#pragma unroll
            for (int k = 0; k < 4; k++) { ck[k] = pcd[3 - k]; sk[k] = psd[3 - k]; }
            applyK<0>(A, ck, sk);
        }
#pragma unroll
        for (int g = 0; g < 16; g++) st[slot((g << 8) | tid)] = A[g];
        __syncthreads();

        // mid: local bit k <-> wire 7-k
#pragma unroll
        for (int g = 0; g < 16; g++) A[g] = st[slot(mid_base | (g << 4))];
        {
            float ck[4], sk[4];
#pragma unroll
            for (int k = 0; k < 4; k++) { ck[k] = pcd[7 - k]; sk[k] = psd[7 - k]; }
            applyK<0>(A, ck, sk);
        }
#pragma unroll
        for (int g = 0; g < 16; g++) st[slot(mid_base | (g << 4))] = A[g];
        __syncthreads();

        // lo: local bit k <-> wire 11-k ; k=0 (wire 11) already merged out
#pragma unroll
        for (int g = 0; g < 16; g++) A[g] = st[slot((tid << 4) | g)];
        {
            float ck[4], sk[4];
#pragma unroll
            for (int k = 1; k < 4; k++) { ck[k] = pcd[11 - k]; sk[k] = psd[11 - k]; }
            ck[0] = 1.f; sk[0] = 0.f;
            applyK<1>(A, ck, sk);
        }
        if (d < DEPTH - 1) {
#pragma unroll
            for (int g = 0; g < 16; g++) st[slot((tid << 4) | g)] = A[g];
            __syncthreads();
        }
        // d == DEPTH-1: amplitudes stay in registers for measurement
    }

    // ---- factorized per-wire measurement (final CNOT perm absorbed):
    // j = (tid<<4)|g.  Wires 0..7: sign depends only on tid -> +-psum.
    // Wires 8..11: sign = parity(popc(tid)) ^ parity(popc(g>>bb)) -> add/sub chains.
    float psum = 0.f, T3 = 0.f, T2 = 0.f, T1 = 0.f, T0 = 0.f;
#pragma unroll
    for (int g = 0; g < 16; g++) {
        const int g3 = (g >> 3) & 1, g2 = (g >> 2) & 1, g1 = (g >> 1) & 1, g0 = g & 1;
        float v = fmaf(A[g].x, A[g].x, A[g].y * A[g].y);
        psum += v;
        T3 += (g3) ? -v : v;                       // bb=3 (wire 8)
        T2 += (g3 ^ g2) ? -v : v;                  // bb=2 (wire 9)
        T1 += (g3 ^ g2 ^ g1) ? -v : v;             // bb=1 (wire 10)
        T0 += (g3 ^ g2 ^ g1 ^ g0) ? -v : v;        // bb=0 (wire 11)
    }

    // per-thread sign bits: wire w (0..7): parity(popc(tid >> (7-w)))
    int pm = 0;
    {
        int par = 0;
#pragma unroll
        for (int w = 0; w < 8; w++) { par ^= (tid >> (7 - w)) & 1; pm |= par << w; }
    }
    const int parT = __popc(tid) & 1;

    float vals[NW];
#pragma unroll
    for (int w = 0; w < 8; w++) vals[w] = ((pm >> w) & 1) ? -psum : psum;
    vals[8]  = parT ? -T3 : T3;
    vals[9]  = parT ? -T2 : T2;
    vals[10] = parT ? -T1 : T1;
    vals[11] = parT ? -T0 : T0;

#pragma unroll
    for (int w = 0; w < NW; w++) {
        float v = vals[w];
#pragma unroll
        for (int o = 16; o > 0; o >>= 1) v += __shfl_xor_sync(0xffffffffu, v, o);
        if (lane == 0) osum[w * 8 + warp] = v;
    }
    __syncthreads();
    if (tid < NW) {
        float t = 0.f;
#pragma unroll
        for (int k = 0; k < 8; k++) t += osum[tid * 8 + k];
        out[b * NW + tid] = t;
    }
}

extern "C" void kernel_launch(void* const* d_in, const int* in_sizes, int n_in,
                              void* d_out, int out_size)
{
    // Identify inputs by element count — robust to metadata ordering.
    const float* x = nullptr;      // 4096*256 = 1048576
    const float* W = nullptr;      // 12*256   = 3072
    const float* params = nullptr; // 4*12*1   = 48
    for (int i = 0; i < n_in; i++) {
        if      (in_sizes[i] == 4096 * 256) x      = (const float*)d_in[i];
        else if (in_sizes[i] == 12 * 256)   W      = (const float*)d_in[i];
        else if (in_sizes[i] == 48)         params = (const float*)d_in[i];
    }
    sim_kernel<<<4096, NT>>>(x, W, params, (float*)d_out);
}

// round 9
// speedup vs baseline: 1.8678x; 1.6067x over previous
#include <cuda_runtime.h>

#define NW 12
#define DIM 4096       // 2^12
#define INDIM 256
#define NT 256

// Swizzles: conflict-free in all three layouts (checked per-layout lane->bank bijection)
__device__ __forceinline__ int s4(int i) { return i ^ ((i >> 4) & 31); }  // float array
__device__ __forceinline__ int s2(int i) { return i ^ ((i >> 4) & 15); }  // float2 array

// In-register 4-level WHT butterflies (bits of local index g)
__device__ __forceinline__ void wht16(float A[16]) {
#pragma unroll
    for (int k = 0; k < 4; k++) {
        const int m = 1 << k;
#pragma unroll
        for (int i = 0; i < 16; i++) {
            if (!(i & m)) {
                float a = A[i], b = A[i | m];
                A[i]     = a + b;
                A[i | m] = a - b;
            }
        }
    }
}

__global__ void __launch_bounds__(NT, 4)
sim_kernel(const float* __restrict__ x, const float* __restrict__ W,
           const float* __restrict__ params, float* __restrict__ out)
{
    // 32 KB buffer: first used as float wht[4096] (16 KB), then reused as float2 cs[4096]
    __shared__ __align__(16) char raw[DIM * 8];
    float*  wht = reinterpret_cast<float*>(raw);
    float2* cs  = reinterpret_cast<float2*>(raw);
    __shared__ float red[NW * 8];
    __shared__ float osum[NW * 8];

    const int tid  = threadIdx.x;
    const int b    = blockIdx.x;
    const int lane = tid & 31;
    const int warp = tid >> 5;

    // ---- zero Walsh-coefficient array ----
#pragma unroll
    for (int g = 0; g < 16; g++) wht[g * NT + tid] = 0.f;

    // ---- angles[b,w] = dot(x[b,:], W[w,:]) ----
    float xv = x[b * INDIM + tid];
#pragma unroll
    for (int w = 0; w < NW; w++) {
        float p = xv * __ldg(&W[w * INDIM + tid]);
#pragma unroll
        for (int o = 16; o > 0; o >>= 1) p += __shfl_xor_sync(0xffffffffu, p, o);
        if (lane == 0) red[w * 8 + warp] = p;
    }
    __syncthreads();

    // ---- scatter the 48 Walsh coefficients of the phase function ----
    // RX(theta) on wire v followed by k CNOT-chains contributes coefficient
    // -theta/2 at mask = (P_k << v) & 0xFFF, P_4..P_1 = 0x111,0x333,0x555,0xFFF
    // (rows of C^{-k}, C = the chain's GF2 map). Data layer merges with d=0 (both k=4).
    if (tid < NW) {
        const int v = tid;
        float a = 0.f;
#pragma unroll
        for (int k = 0; k < 8; k++) a += red[v * 8 + k];
        int   ms[4];
        float vs[4];
        ms[0] = (0x111 << v) & 0xFFF; vs[0] = -0.5f * (a + params[v]);   // init + depth0
        ms[1] = (0x333 << v) & 0xFFF; vs[1] = -0.5f * params[NW + v];    // depth1
        ms[2] = (0x555 << v) & 0xFFF; vs[2] = -0.5f * params[2 * NW + v];// depth2
        ms[3] = (0xFFF << v) & 0xFFF; vs[3] = -0.5f * params[3 * NW + v];// depth3
        // merge duplicate masks (happens for v >= 10); masks' lowest bit = v,
        // so no cross-thread collisions.
#pragma unroll
        for (int i = 0; i < 4; i++) {
            if (ms[i] < 0) continue;
#pragma unroll
            for (int j = i + 1; j < 4; j++)
                if (ms[j] == ms[i]) { vs[i] += vs[j]; ms[j] = -1; }
            wht[s4(ms[i])] += vs[i];
        }
    }
    __syncthreads();

    // ---- fast WHT, 12 levels in 3 register-resident phases ----
    float A[16];
    // HI: idx = (g<<8)|tid, bits 11:8 local
#pragma unroll
    for (int g = 0; g < 16; g++) A[g] = wht[s4((g << 8) | tid)];
    wht16(A);
#pragma unroll
    for (int g = 0; g < 16; g++) wht[s4((g << 8) | tid)] = A[g];
    __syncthreads();
    // MID: idx = mb | (g<<4), bits 7:4 local
    const int mb = ((tid >> 4) << 8) | (tid & 15);
#pragma unroll
    for (int g = 0; g < 16; g++) A[g] = wht[s4(mb | (g << 4))];
    wht16(A);
#pragma unroll
    for (int g = 0; g < 16; g++) wht[s4(mb | (g << 4))] = A[g];
    __syncthreads();
    // LO: idx = (tid<<4)|g, bits 3:0 local
#pragma unroll
    for (int g = 0; g < 16; g++) A[g] = wht[s4((tid << 4) | g)];
    wht16(A);
    __syncthreads();   // all LO reads done before cs overwrites the buffer

    // ---- phases -> (cos, sin); publish to smem for cross-thread correlations ----
    float cA[16], sA[16];
#pragma unroll
    for (int g = 0; g < 16; g++) sincosf(A[g], &sA[g], &cA[g]);
#pragma unroll
    for (int g = 0; g < 16; g++) cs[s2((tid << 4) | g)] = make_float2(cA[g], sA[g]);
    __syncthreads();

    // ---- <Z_w> = 2^-12 sum_y cos(phi(y+e_w) - phi(y)) = 2^-12 sum (c c' + s s') ----
    // wires 0..3: partner differs in a register-local bit of g
#pragma unroll
    for (int w = 0; w < 4; w++) {
        const int m = 1 << w;
        float acc = 0.f;
#pragma unroll
        for (int g = 0; g < 16; g++)
            acc = fmaf(cA[g], cA[g ^ m], fmaf(sA[g], sA[g ^ m], acc));
#pragma unroll
        for (int o = 16; o > 0; o >>= 1) acc += __shfl_xor_sync(0xffffffffu, acc, o);
        if (lane == 0) osum[w * 8 + warp] = acc;
    }
    // wires 4..11: partner differs in a tid bit -> read partner (c,s) from smem
#pragma unroll
    for (int w = 4; w < NW; w++) {
        const int pt = tid ^ (1 << (w - 4));
        float acc = 0.f;
#pragma unroll
        for (int g = 0; g < 16; g++) {
            float2 p = cs[s2((pt << 4) | g)];
            acc = fmaf(cA[g], p.x, fmaf(sA[g], p.y, acc));
        }
#pragma unroll
        for (int o = 16; o > 0; o >>= 1) acc += __shfl_xor_sync(0xffffffffu, acc, o);
        if (lane == 0) osum[w * 8 + warp] = acc;
    }
    __syncthreads();
    if (tid < NW) {
        float t = 0.f;
#pragma unroll
        for (int k = 0; k < 8; k++) t += osum[tid * 8 + k];
        out[b * NW + tid] = t * (1.f / 4096.f);
    }
}

extern "C" void kernel_launch(void* const* d_in, const int* in_sizes, int n_in,
                              void* d_out, int out_size)
{
    // Identify inputs by element count — robust to metadata ordering.
    const float* x = nullptr;      // 4096*256 = 1048576
    const float* W = nullptr;      // 12*256   = 3072
    const float* params = nullptr; // 4*12*1   = 48
    for (int i = 0; i < n_in; i++) {
        if      (in_sizes[i] == 4096 * 256) x      = (const float*)d_in[i];
        else if (in_sizes[i] == 12 * 256)   W      = (const float*)d_in[i];
        else if (in_sizes[i] == 48)         params = (const float*)d_in[i];
    }
    sim_kernel<<<4096, NT>>>(x, W, params, (float*)d_out);
}

// round 10
// speedup vs baseline: 2.3163x; 1.2401x over previous
#include <cuda_runtime.h>

#define NW 12
#define DIM 4096       // 2^12
#define INDIM 256
#define NT 256

// Swizzles: conflict-free in all layouts (2 lanes per bank-pair for 64-bit, optimal)
__device__ __forceinline__ int s4(int i) { return i ^ ((i >> 4) & 31); }  // float array
__device__ __forceinline__ int s2(int i) { return i ^ ((i >> 4) & 15); }  // float2 array

// In-register 4-level WHT butterflies (bits of local index)
__device__ __forceinline__ void wht16(float A[16]) {
#pragma unroll
    for (int k = 0; k < 4; k++) {
        const int m = 1 << k;
#pragma unroll
        for (int i = 0; i < 16; i++) {
            if (!(i & m)) {
                float a = A[i], b = A[i | m];
                A[i]     = a + b;
                A[i | m] = a - b;
            }
        }
    }
}

__global__ void __launch_bounds__(NT, 4)
sim_kernel(const float* __restrict__ x, const float* __restrict__ W,
           const float* __restrict__ params, float* __restrict__ out)
{
    // 32 KB buffer: first float wht[4096] (16 KB), then reused as float2 cs[4096]
    __shared__ __align__(16) char raw[DIM * 8];
    float*  wht = reinterpret_cast<float*>(raw);
    float2* cs  = reinterpret_cast<float2*>(raw);
    __shared__ float red[NW * 8];
    __shared__ float osum[NW * 8];

    const int tid  = threadIdx.x;
    const int b    = blockIdx.x;
    const int lane = tid & 31;
    const int warp = tid >> 5;

    // ---- zero Walsh-coefficient array ----
#pragma unroll
    for (int g = 0; g < 16; g++) wht[g * NT + tid] = 0.f;

    // ---- angles[b,w] = dot(x[b,:], W[w,:]) ----
    float xv = x[b * INDIM + tid];
#pragma unroll
    for (int w = 0; w < NW; w++) {
        float p = xv * __ldg(&W[w * INDIM + tid]);
#pragma unroll
        for (int o = 16; o > 0; o >>= 1) p += __shfl_xor_sync(0xffffffffu, p, o);
        if (lane == 0) red[w * 8 + warp] = p;
    }
    __syncthreads();

    // ---- scatter the 48 Walsh coefficients of the phase function ----
    // RX(theta) on wire v followed by k CNOT-chains contributes -theta/2 at
    // mask = (P_k << v) & 0xFFF, P_4..P_1 = 0x111,0x333,0x555,0xFFF.
    if (tid < NW) {
        const int v = tid;
        float a = 0.f;
#pragma unroll
        for (int k = 0; k < 8; k++) a += red[v * 8 + k];
        int   ms[4];
        float vs[4];
        ms[0] = (0x111 << v) & 0xFFF; vs[0] = -0.5f * (a + params[v]);    // init + depth0
        ms[1] = (0x333 << v) & 0xFFF; vs[1] = -0.5f * params[NW + v];     // depth1
        ms[2] = (0x555 << v) & 0xFFF; vs[2] = -0.5f * params[2 * NW + v]; // depth2
        ms[3] = (0xFFF << v) & 0xFFF; vs[3] = -0.5f * params[3 * NW + v]; // depth3
#pragma unroll
        for (int i = 0; i < 4; i++) {
            if (ms[i] < 0) continue;
#pragma unroll
            for (int j = i + 1; j < 4; j++)
                if (ms[j] == ms[i]) { vs[i] += vs[j]; ms[j] = -1; }
            wht[s4(ms[i])] += vs[i];
        }
    }
    __syncthreads();

    // ---- real fast WHT (phases), 12 levels in 3 register-resident phases ----
    float cA[16], sA[16];
    {
        float A[16];
        // HI: idx=(g<<8)|tid
#pragma unroll
        for (int g = 0; g < 16; g++) A[g] = wht[s4((g << 8) | tid)];
        wht16(A);
#pragma unroll
        for (int g = 0; g < 16; g++) wht[s4((g << 8) | tid)] = A[g];
        __syncthreads();
        // MID: idx = mb | (g<<4)
        const int mb = ((tid >> 4) << 8) | (tid & 15);
#pragma unroll
        for (int g = 0; g < 16; g++) A[g] = wht[s4(mb | (g << 4))];
        wht16(A);
#pragma unroll
        for (int g = 0; g < 16; g++) wht[s4(mb | (g << 4))] = A[g];
        __syncthreads();
        // LO: idx = (tid<<4)|g
#pragma unroll
        for (int g = 0; g < 16; g++) A[g] = wht[s4((tid << 4) | g)];
        wht16(A);
        // phases -> unit complex u(y) = (cos, sin)
#pragma unroll
        for (int g = 0; g < 16; g++) sincosf(A[g], &sA[g], &cA[g]);
    }
    __syncthreads();   // all real-WHT reads done before complex buffer overwrites

    // ---- complex WHT of u (componentwise real WHTs), LO -> MID -> HI ----
    // LO level: y bits 3:0 are register-local right now
    wht16(cA); wht16(sA);
#pragma unroll
    for (int g = 0; g < 16; g++) cs[s2((tid << 4) | g)] = make_float2(cA[g], sA[g]);
    __syncthreads();
    // MID level
    {
        const int mb = ((tid >> 4) << 8) | (tid & 15);
#pragma unroll
        for (int g = 0; g < 16; g++) {
            float2 p = cs[s2(mb | (g << 4))];
            cA[g] = p.x; sA[g] = p.y;
        }
        wht16(cA); wht16(sA);
#pragma unroll
        for (int g = 0; g < 16; g++) cs[s2(mb | (g << 4))] = make_float2(cA[g], sA[g]);
    }
    __syncthreads();
    // HI level: m = (g<<8)|tid
#pragma unroll
    for (int g = 0; g < 16; g++) {
        float2 p = cs[s2((g << 8) | tid)];
        cA[g] = p.x; sA[g] = p.y;
    }
    wht16(cA); wht16(sA);

    // ---- Parseval: <Z_w> = 2^-24 sum_m |U(m)|^2 (-1)^{m_w},  m=(g<<8)|tid ----
    float P[16];
#pragma unroll
    for (int g = 0; g < 16; g++)
        P[g] = fmaf(cA[g], cA[g], sA[g] * sA[g]);

    float psum = 0.f, T8 = 0.f, T9 = 0.f, T10 = 0.f, T11 = 0.f;
#pragma unroll
    for (int g = 0; g < 16; g++) {
        float v = P[g];
        psum += v;
        T8  += (g & 1) ? -v : v;   // m bit 8  = g bit 0
        T9  += (g & 2) ? -v : v;   // m bit 9  = g bit 1
        T10 += (g & 4) ? -v : v;   // m bit 10 = g bit 2
        T11 += (g & 8) ? -v : v;   // m bit 11 = g bit 3
    }

    float vals[NW];
#pragma unroll
    for (int w = 0; w < 8; w++) vals[w] = ((tid >> w) & 1) ? -psum : psum;  // m bit w = tid bit w
    vals[8] = T8; vals[9] = T9; vals[10] = T10; vals[11] = T11;

#pragma unroll
    for (int w = 0; w < NW; w++) {
        float v = vals[w];
#pragma unroll
        for (int o = 16; o > 0; o >>= 1) v += __shfl_xor_sync(0xffffffffu, v, o);
        if (lane == 0) osum[w * 8 + warp] = v;
    }
    __syncthreads();
    if (tid < NW) {
        float t = 0.f;
#pragma unroll
        for (int k = 0; k < 8; k++) t += osum[tid * 8 + k];
        out[b * NW + tid] = t * (1.f / 16777216.f);   // 2^-24
    }
}

extern "C" void kernel_launch(void* const* d_in, const int* in_sizes, int n_in,
                              void* d_out, int out_size)
{
    // Identify inputs by element count — robust to metadata ordering.
    const float* x = nullptr;      // 4096*256 = 1048576
    const float* W = nullptr;      // 12*256   = 3072
    const float* params = nullptr; // 4*12*1   = 48
    for (int i = 0; i < n_in; i++) {
        if      (in_sizes[i] == 4096 * 256) x      = (const float*)d_in[i];
        else if (in_sizes[i] == 12 * 256)   W      = (const float*)d_in[i];
        else if (in_sizes[i] == 48)         params = (const float*)d_in[i];
    }
    sim_kernel<<<4096, NT>>>(x, W, params, (float*)d_out);
}

// round 11
// speedup vs baseline: 3.1759x; 1.3711x over previous
#include <cuda_runtime.h>

#define NW 12
#define DIM 4096       // 2^12
#define INDIM 256
#define NT 256

// Swizzle for float2 array: conflict-free in both (tid<<4)|g and mid layouts
__device__ __forceinline__ int s2(int i) { return i ^ ((i >> 4) & 15); }

// In-register 4-level WHT butterflies (bits of local index)
__device__ __forceinline__ void wht16(float A[16]) {
#pragma unroll
    for (int k = 0; k < 4; k++) {
        const int m = 1 << k;
#pragma unroll
        for (int i = 0; i < 16; i++) {
            if (!(i & m)) {
                float a = A[i], b = A[i | m];
                A[i]     = a + b;
                A[i | m] = a - b;
            }
        }
    }
}

__global__ void __launch_bounds__(NT, 4)
sim_kernel(const float* __restrict__ x, const float* __restrict__ W,
           const float* __restrict__ params, float* __restrict__ out)
{
    __shared__ __align__(16) float2 cs[DIM];   // 32 KB complex WHT buffer
    __shared__ float red[NW * 8];
    __shared__ float cv[NW * 4];               // 48 Walsh coefficients
    __shared__ float osum[NW * 8];

    const int tid  = threadIdx.x;
    const int b    = blockIdx.x;
    const int lane = tid & 31;
    const int warp = tid >> 5;

    // ---- angles[b,w] = dot(x[b,:], W[w,:]) ----
    float xv = x[b * INDIM + tid];
#pragma unroll
    for (int w = 0; w < NW; w++) {
        float p = xv * __ldg(&W[w * INDIM + tid]);
#pragma unroll
        for (int o = 16; o > 0; o >>= 1) p += __shfl_xor_sync(0xffffffffu, p, o);
        if (lane == 0) red[w * 8 + warp] = p;
    }
    __syncthreads();

    // ---- 48 Walsh coefficients: RX(theta) on wire v after which k CNOT-chains
    //      remain contributes -theta/2 at mask (P_k << v) & 0xFFF.
    if (tid < NW) {
        const int v = tid;
        float a = 0.f;
#pragma unroll
        for (int k = 0; k < 8; k++) a += red[v * 8 + k];
        cv[v * 4 + 0] = -0.5f * (a + params[v]);     // init + depth0 (P=0x111)
        cv[v * 4 + 1] = -0.5f * params[NW + v];      // depth1       (P=0x333)
        cv[v * 4 + 2] = -0.5f * params[2 * NW + v];  // depth2       (P=0x555)
        cv[v * 4 + 3] = -0.5f * params[3 * NW + v];  // depth3       (P=0xFFF)
    }
    __syncthreads();

    // ---- sparse phase evaluation: phi(y) = sum_t a_t (-1)^{<m_t, y>}
    // y = (tid<<4) | g. Bucket by mask low nibble (compile-time), sign from
    // parity(mask_hi & tid), then WHT16 over buckets gives phi for all 16 g.
    float cA[16], sA[16];
    {
        float B[16];
#pragma unroll
        for (int n = 0; n < 16; n++) B[n] = 0.f;

        const int Pm[4] = {0x111, 0x333, 0x555, 0xFFF};
#pragma unroll
        for (int v = 0; v < NW; v++) {
#pragma unroll
            for (int i = 0; i < 4; i++) {
                const int m   = (Pm[i] << v) & 0xFFF;   // compile-time constant
                const int mhi = m >> 4, mlo = m & 15;
                float a = cv[v * 4 + i];                 // uniform LDS broadcast
                B[mlo] += (__popc(mhi & tid) & 1) ? -a : a;
            }
        }
        wht16(B);                                        // B[g] = phi((tid<<4)|g)
#pragma unroll
        for (int g = 0; g < 16; g++) __sincosf(B[g], &sA[g], &cA[g]);
    }

    // ---- complex WHT of u = e^{i phi} (componentwise real WHTs), LO -> MID -> HI
    wht16(cA); wht16(sA);                                // LO: y bits 3:0 local
#pragma unroll
    for (int g = 0; g < 16; g++) cs[s2((tid << 4) | g)] = make_float2(cA[g], sA[g]);
    __syncthreads();
    {   // MID: bits 7:4 local
        const int mb = ((tid >> 4) << 8) | (tid & 15);
#pragma unroll
        for (int g = 0; g < 16; g++) {
            float2 p = cs[s2(mb | (g << 4))];
            cA[g] = p.x; sA[g] = p.y;
        }
        wht16(cA); wht16(sA);
#pragma unroll
        for (int g = 0; g < 16; g++) cs[s2(mb | (g << 4))] = make_float2(cA[g], sA[g]);
    }
    __syncthreads();
    // HI: m = (g<<8)|tid
#pragma unroll
    for (int g = 0; g < 16; g++) {
        float2 p = cs[s2((g << 8) | tid)];
        cA[g] = p.x; sA[g] = p.y;
    }
    wht16(cA); wht16(sA);

    // ---- Parseval: <Z_w> = 2^-24 sum_m |U(m)|^2 (-1)^{m_w},  m=(g<<8)|tid ----
    float psum = 0.f, T8 = 0.f, T9 = 0.f, T10 = 0.f, T11 = 0.f;
#pragma unroll
    for (int g = 0; g < 16; g++) {
        float v = fmaf(cA[g], cA[g], sA[g] * sA[g]);
        psum += v;
        T8  += (g & 1) ? -v : v;   // m bit 8  = g bit 0
        T9  += (g & 2) ? -v : v;   // m bit 9  = g bit 1
        T10 += (g & 4) ? -v : v;   // m bit 10 = g bit 2
        T11 += (g & 8) ? -v : v;   // m bit 11 = g bit 3
    }

    float vals[NW];
#pragma unroll
    for (int w = 0; w < 8; w++) vals[w] = ((tid >> w) & 1) ? -psum : psum;  // m bit w = tid bit w
    vals[8] = T8; vals[9] = T9; vals[10] = T10; vals[11] = T11;

#pragma unroll
    for (int w = 0; w < NW; w++) {
        float v = vals[w];
#pragma unroll
        for (int o = 16; o > 0; o >>= 1) v += __shfl_xor_sync(0xffffffffu, v, o);
        if (lane == 0) osum[w * 8 + warp] = v;
    }
    __syncthreads();
    if (tid < NW) {
        float t = 0.f;
#pragma unroll
        for (int k = 0; k < 8; k++) t += osum[tid * 8 + k];
        out[b * NW + tid] = t * (1.f / 16777216.f);   // 2^-24
    }
}

extern "C" void kernel_launch(void* const* d_in, const int* in_sizes, int n_in,
                              void* d_out, int out_size)
{
    // Identify inputs by element count — robust to metadata ordering.
    const float* x = nullptr;      // 4096*256 = 1048576
    const float* W = nullptr;      // 12*256   = 3072
    const float* params = nullptr; // 4*12*1   = 48
    for (int i = 0; i < n_in; i++) {
        if      (in_sizes[i] == 4096 * 256) x      = (const float*)d_in[i];
        else if (in_sizes[i] == 12 * 256)   W      = (const float*)d_in[i];
        else if (in_sizes[i] == 48)         params = (const float*)d_in[i];
    }
    sim_kernel<<<4096, NT>>>(x, W, params, (float*)d_out);
}

// round 12
// speedup vs baseline: 3.3147x; 1.0437x over previous
#include <cuda_runtime.h>

#define NW 12
#define DIM 4096       // 2^12
#define INDIM 256
#define NT 256

// Swizzle for float2 array: conflict-free in all three exchange layouts
__device__ __forceinline__ int s2(int i) { return i ^ ((i >> 4) & 15); }

// In-register 4-level WHT butterflies (bits of local index)
__device__ __forceinline__ void wht16(float A[16]) {
#pragma unroll
    for (int k = 0; k < 4; k++) {
        const int m = 1 << k;
#pragma unroll
        for (int i = 0; i < 16; i++) {
            if (!(i & m)) {
                float a = A[i], b = A[i | m];
                A[i]     = a + b;
                A[i | m] = a - b;
            }
        }
    }
}

__global__ void __launch_bounds__(NT, 4)
sim_kernel(const float* __restrict__ x, const float* __restrict__ W,
           const float* __restrict__ params, float* __restrict__ out)
{
    __shared__ __align__(16) float2 cs[DIM];   // 32 KB complex WHT buffer
    __shared__ float red[NW * 32];             // angle partials (3-level reduced)
    __shared__ float cv[NW * 4];               // 48 Walsh coefficients
    __shared__ float wA[5 * 8];                // warp-WHT comps: wires 0..4 per warp
    __shared__ float w0[8];                    // warp totals of psum (wires 5..7)
    __shared__ float wT[4 * 32];               // T8..T11 partials

    const int tid  = threadIdx.x;
    const int b    = blockIdx.x;
    const int lane = tid & 31;
    const int warp = tid >> 5;

    // ---- angles[b,w] = dot(x[b,:], W[w,:]) ; 3 shfl levels + smem finish ----
    float xv = x[b * INDIM + tid];
#pragma unroll
    for (int w = 0; w < NW; w++) {
        float p = xv * __ldg(&W[w * INDIM + tid]);
        p += __shfl_xor_sync(0xffffffffu, p, 16);
        p += __shfl_xor_sync(0xffffffffu, p, 8);
        p += __shfl_xor_sync(0xffffffffu, p, 4);
        // lanes 0..3 hold the 4 distinct mod-4 group sums
        if (lane < 4) red[w * 32 + warp * 4 + lane] = p;
    }
    __syncthreads();

    // ---- 48 Walsh coefficients: RX(theta) on wire v with k CNOT-chains after it
    //      contributes -theta/2 at mask (P_k << v) & 0xFFF.
    if (tid < NW) {
        const int v = tid;
        float a = 0.f;
#pragma unroll
        for (int k = 0; k < 32; k++) a += red[v * 32 + k];
        cv[v * 4 + 0] = -0.5f * (a + params[v]);     // init + depth0 (P=0x111)
        cv[v * 4 + 1] = -0.5f * params[NW + v];      // depth1       (P=0x333)
        cv[v * 4 + 2] = -0.5f * params[2 * NW + v];  // depth2       (P=0x555)
        cv[v * 4 + 3] = -0.5f * params[3 * NW + v];  // depth3       (P=0xFFF)
    }
    __syncthreads();

    // ---- sparse phase evaluation: phi(y) = sum_t a_t (-1)^{<m_t, y>}
    // y = (tid<<4) | g. Bucket by mask low nibble (compile-time), sign from
    // parity(mask_hi & tid), then WHT16 over buckets gives phi for all 16 g.
    float cA[16], sA[16];
    {
        float B[16];
#pragma unroll
        for (int n = 0; n < 16; n++) B[n] = 0.f;

        const int Pm[4] = {0x111, 0x333, 0x555, 0xFFF};
#pragma unroll
        for (int v = 0; v < NW; v++) {
#pragma unroll
            for (int i = 0; i < 4; i++) {
                const int m   = (Pm[i] << v) & 0xFFF;   // compile-time constant
                const int mhi = m >> 4, mlo = m & 15;
                float a = cv[v * 4 + i];                 // uniform LDS broadcast
                B[mlo] += (__popc(mhi & tid) & 1) ? -a : a;
            }
        }
        wht16(B);                                        // B[g] = phi((tid<<4)|g)
#pragma unroll
        for (int g = 0; g < 16; g++) __sincosf(B[g], &sA[g], &cA[g]);
    }

    // ---- complex WHT of u = e^{i phi} (componentwise real WHTs), LO -> MID -> HI
    wht16(cA); wht16(sA);                                // LO: y bits 3:0 local
#pragma unroll
    for (int g = 0; g < 16; g++) cs[s2((tid << 4) | g)] = make_float2(cA[g], sA[g]);
    __syncthreads();
    {   // MID: bits 7:4 local
        const int mb = ((tid >> 4) << 8) | (tid & 15);
#pragma unroll
        for (int g = 0; g < 16; g++) {
            float2 p = cs[s2(mb | (g << 4))];
            cA[g] = p.x; sA[g] = p.y;
        }
        wht16(cA); wht16(sA);
#pragma unroll
        for (int g = 0; g < 16; g++) cs[s2(mb | (g << 4))] = make_float2(cA[g], sA[g]);
    }
    __syncthreads();
    // HI: m = (g<<8)|tid
#pragma unroll
    for (int g = 0; g < 16; g++) {
        float2 p = cs[s2((g << 8) | tid)];
        cA[g] = p.x; sA[g] = p.y;
    }
    wht16(cA); wht16(sA);

    // ---- Parseval: <Z_w> = 2^-24 sum_m |U(m)|^2 (-1)^{m_w},  m=(g<<8)|tid ----
    float psum = 0.f, T8 = 0.f, T9 = 0.f, T10 = 0.f, T11 = 0.f;
#pragma unroll
    for (int g = 0; g < 16; g++) {
        float v = fmaf(cA[g], cA[g], sA[g] * sA[g]);
        psum += v;
        T8  += (g & 1) ? -v : v;   // m bit 8  = g bit 0
        T9  += (g & 2) ? -v : v;   // m bit 9  = g bit 1
        T10 += (g & 4) ? -v : v;   // m bit 10 = g bit 2
        T11 += (g & 8) ? -v : v;   // m bit 11 = g bit 3
    }

    // Warp-WHT on psum: lane L ends with sum_t (-1)^{<L,t>} psum_t over the warp.
    {
        float v = psum;
#pragma unroll
        for (int o = 1; o < 32; o <<= 1) {
            float r = __shfl_xor_sync(0xffffffffu, v, o);
            v = (lane & o) ? (r - v) : (v + r);
        }
        if (lane == 0) w0[warp] = v;                       // component 0 (warp total)
        else if ((lane & (lane - 1)) == 0)                 // lanes 1,2,4,8,16
            wA[__popc(lane - 1) * 8 + warp] = v;           // wire = log2(lane)
    }
    // T8..T11: 3 shfl levels, lanes 0..3 store the 4 group sums
    {
#pragma unroll
        for (int o = 16; o >= 4; o >>= 1) {
            T8  += __shfl_xor_sync(0xffffffffu, T8,  o);
            T9  += __shfl_xor_sync(0xffffffffu, T9,  o);
            T10 += __shfl_xor_sync(0xffffffffu, T10, o);
            T11 += __shfl_xor_sync(0xffffffffu, T11, o);
        }
        if (lane < 4) {
            wT[0 * 32 + warp * 4 + lane] = T8;
            wT[1 * 32 + warp * 4 + lane] = T9;
            wT[2 * 32 + warp * 4 + lane] = T10;
            wT[3 * 32 + warp * 4 + lane] = T11;
        }
    }
    __syncthreads();

    if (tid < NW) {
        float t = 0.f;
        const int w = tid;
        if (w < 5) {                       // tid bit w = lane bit w
#pragma unroll
            for (int k = 0; k < 8; k++) t += wA[w * 8 + k];
        } else if (w < 8) {                // tid bit w = warp bit (w-5)
#pragma unroll
            for (int k = 0; k < 8; k++)
                t += ((k >> (w - 5)) & 1) ? -w0[k] : w0[k];
        } else {                           // wires 8..11 from T partials
#pragma unroll
            for (int j = 0; j < 32; j++) t += wT[(w - 8) * 32 + j];
        }
        out[b * NW + w] = t * (1.f / 16777216.f);   // 2^-24
    }
}

extern "C" void kernel_launch(void* const* d_in, const int* in_sizes, int n_in,
                              void* d_out, int out_size)
{
    // Identify inputs by element count — robust to metadata ordering.
    const float* x = nullptr;      // 4096*256 = 1048576
    const float* W = nullptr;      // 12*256   = 3072
    const float* params = nullptr; // 4*12*1   = 48
    for (int i = 0; i < n_in; i++) {
        if      (in_sizes[i] == 4096 * 256) x      = (const float*)d_in[i];
        else if (in_sizes[i] == 12 * 256)   W      = (const float*)d_in[i];
        else if (in_sizes[i] == 48)         params = (const float*)d_in[i];
    }
    sim_kernel<<<4096, NT>>>(x, W, params, (float*)d_out);
}

// round 13
// speedup vs baseline: 3.6031x; 1.0870x over previous
#include <cuda_runtime.h>
#include <cstdint>

#define NW 12
#define DIM 4096       // 2^12
#define INDIM 256
#define NT 256

// Swizzle for 64-bit elements: conflict-free in all three exchange layouts
__device__ __forceinline__ int s2(int i) { return i ^ ((i >> 4) & 15); }

// ---- packed f32x2 ops (sm_103a) ----
__device__ __forceinline__ uint64_t addx2(uint64_t a, uint64_t b) {
    uint64_t r; asm("add.rn.f32x2 %0, %1, %2;" : "=l"(r) : "l"(a), "l"(b)); return r;
}
__device__ __forceinline__ uint64_t subx2(uint64_t a, uint64_t b) {
    uint64_t r; asm("sub.rn.f32x2 %0, %1, %2;" : "=l"(r) : "l"(a), "l"(b)); return r;
}
__device__ __forceinline__ uint64_t packx2(float lo, float hi) {
    uint64_t r; asm("mov.b64 %0, {%1, %2};" : "=l"(r) : "f"(lo), "f"(hi)); return r;
}
__device__ __forceinline__ void unpackx2(float& lo, float& hi, uint64_t v) {
    asm("mov.b64 {%0, %1}, %2;" : "=f"(lo), "=f"(hi) : "l"(v));
}

// In-register 4-level WHT butterflies, scalar (for phases)
__device__ __forceinline__ void wht16(float A[16]) {
#pragma unroll
    for (int k = 0; k < 4; k++) {
        const int m = 1 << k;
#pragma unroll
        for (int i = 0; i < 16; i++) {
            if (!(i & m)) {
                float a = A[i], b = A[i | m];
                A[i]     = a + b;
                A[i | m] = a - b;
            }
        }
    }
}

// In-register 4-level WHT butterflies on packed (cos,sin) pairs
__device__ __forceinline__ void wht16p(uint64_t U[16]) {
#pragma unroll
    for (int k = 0; k < 4; k++) {
        const int m = 1 << k;
#pragma unroll
        for (int i = 0; i < 16; i++) {
            if (!(i & m)) {
                uint64_t a = U[i], b = U[i | m];
                U[i]     = addx2(a, b);
                U[i | m] = subx2(a, b);
            }
        }
    }
}

__global__ void __launch_bounds__(NT, 4)
sim_kernel(const float* __restrict__ x, const float* __restrict__ W,
           const float* __restrict__ params, float* __restrict__ out)
{
    __shared__ __align__(16) uint64_t cs[DIM]; // 32 KB packed (cos,sin) WHT buffer
    __shared__ float red[NW * 32];             // angle partials (3-level reduced)
    __shared__ float cv[NW * 4];               // 48 Walsh coefficients
    __shared__ float wA[5 * 8];                // warp-WHT comps: wires 0..4 per warp
    __shared__ float w0[8];                    // warp totals of psum (wires 5..7)
    __shared__ float wT[4 * 32];               // T8..T11 partials

    const int tid  = threadIdx.x;
    const int b    = blockIdx.x;
    const int lane = tid & 31;
    const int warp = tid >> 5;

    // ---- angles[b,w] = dot(x[b,:], W[w,:]) ; 3 shfl levels + smem finish ----
    float xv = x[b * INDIM + tid];
#pragma unroll
    for (int w = 0; w < NW; w++) {
        float p = xv * __ldg(&W[w * INDIM + tid]);
        p += __shfl_xor_sync(0xffffffffu, p, 16);
        p += __shfl_xor_sync(0xffffffffu, p, 8);
        p += __shfl_xor_sync(0xffffffffu, p, 4);
        if (lane < 4) red[w * 32 + warp * 4 + lane] = p;
    }
    __syncthreads();

    // ---- 48 Walsh coefficients: RX(theta) on wire v with k CNOT-chains after it
    //      contributes -theta/2 at mask (P_k << v) & 0xFFF.
    if (tid < NW) {
        const int v = tid;
        float a = 0.f;
#pragma unroll
        for (int k = 0; k < 32; k++) a += red[v * 32 + k];
        cv[v * 4 + 0] = -0.5f * (a + params[v]);     // init + depth0 (P=0x111)
        cv[v * 4 + 1] = -0.5f * params[NW + v];      // depth1       (P=0x333)
        cv[v * 4 + 2] = -0.5f * params[2 * NW + v];  // depth2       (P=0x555)
        cv[v * 4 + 3] = -0.5f * params[3 * NW + v];  // depth3       (P=0xFFF)
    }
    __syncthreads();

    // ---- sparse phase evaluation: phi(y) = sum_t a_t (-1)^{<m_t, y>}
    // y = (tid<<4) | g. Bucket by mask low nibble (compile-time), sign from
    // parity(mask_hi & tid), then WHT16 over buckets gives phi for all 16 g.
    uint64_t U[16];                 // packed (cos, sin)
    {
        float B[16];
#pragma unroll
        for (int n = 0; n < 16; n++) B[n] = 0.f;

        const int Pm[4] = {0x111, 0x333, 0x555, 0xFFF};
#pragma unroll
        for (int v = 0; v < NW; v++) {
#pragma unroll
            for (int i = 0; i < 4; i++) {
                const int m   = (Pm[i] << v) & 0xFFF;   // compile-time constant
                const int mhi = m >> 4, mlo = m & 15;
                float a = cv[v * 4 + i];                 // uniform LDS broadcast
                B[mlo] += (__popc(mhi & tid) & 1) ? -a : a;
            }
        }
        wht16(B);                                        // B[g] = phi((tid<<4)|g)
#pragma unroll
        for (int g = 0; g < 16; g++) {
            float sv, cvv; __sincosf(B[g], &sv, &cvv);
            U[g] = packx2(cvv, sv);
        }
    }

    // ---- complex WHT of u = e^{i phi}: packed butterflies, LO -> MID -> HI ----
    wht16p(U);                                           // LO: y bits 3:0 local
#pragma unroll
    for (int g = 0; g < 16; g++) cs[s2((tid << 4) | g)] = U[g];
    __syncthreads();
    {   // MID: bits 7:4 local
        const int mb = ((tid >> 4) << 8) | (tid & 15);
#pragma unroll
        for (int g = 0; g < 16; g++) U[g] = cs[s2(mb | (g << 4))];
        wht16p(U);
#pragma unroll
        for (int g = 0; g < 16; g++) cs[s2(mb | (g << 4))] = U[g];
    }
    __syncthreads();
    // HI: m = (g<<8)|tid
#pragma unroll
    for (int g = 0; g < 16; g++) U[g] = cs[s2((g << 8) | tid)];
    wht16p(U);

    // ---- Parseval: <Z_w> = 2^-24 sum_m |U(m)|^2 (-1)^{m_w},  m=(g<<8)|tid ----
    float psum = 0.f, T8 = 0.f, T9 = 0.f, T10 = 0.f, T11 = 0.f;
#pragma unroll
    for (int g = 0; g < 16; g++) {
        float c, s; unpackx2(c, s, U[g]);
        float v = fmaf(c, c, s * s);
        psum += v;
        T8  += (g & 1) ? -v : v;   // m bit 8  = g bit 0
        T9  += (g & 2) ? -v : v;   // m bit 9  = g bit 1
        T10 += (g & 4) ? -v : v;   // m bit 10 = g bit 2
        T11 += (g & 8) ? -v : v;   // m bit 11 = g bit 3
    }

    // Warp-WHT on psum: lane L ends with sum_t (-1)^{<L,t>} psum_t over the warp.
    {
        float v = psum;
#pragma unroll
        for (int o = 1; o < 32; o <<= 1) {
            float r = __shfl_xor_sync(0xffffffffu, v, o);
            v = (lane & o) ? (r - v) : (v + r);
        }
        if (lane == 0) w0[warp] = v;                       // component 0 (warp total)
        else if ((lane & (lane - 1)) == 0)                 // lanes 1,2,4,8,16
            wA[__popc(lane - 1) * 8 + warp] = v;           // wire = log2(lane)
    }
    // T8..T11: 3 shfl levels, lanes 0..3 store the 4 group sums
    {
#pragma unroll
        for (int o = 16; o >= 4; o >>= 1) {
            T8  += __shfl_xor_sync(0xffffffffu, T8,  o);
            T9  += __shfl_xor_sync(0xffffffffu, T9,  o);
            T10 += __shfl_xor_sync(0xffffffffu, T10, o);
            T11 += __shfl_xor_sync(0xffffffffu, T11, o);
        }
        if (lane < 4) {
            wT[0 * 32 + warp * 4 + lane] = T8;
            wT[1 * 32 + warp * 4 + lane] = T9;
            wT[2 * 32 + warp * 4 + lane] = T10;
            wT[3 * 32 + warp * 4 + lane] = T11;
        }
    }
    __syncthreads();

    if (tid < NW) {
        float t = 0.f;
        const int w = tid;
        if (w < 5) {                       // tid bit w = lane bit w
#pragma unroll
            for (int k = 0; k < 8; k++) t += wA[w * 8 + k];
        } else if (w < 8) {                // tid bit w = warp bit (w-5)
#pragma unroll
            for (int k = 0; k < 8; k++)
                t += ((k >> (w - 5)) & 1) ? -w0[k] : w0[k];
        } else {                           // wires 8..11 from T partials
#pragma unroll
            for (int j = 0; j < 32; j++) t += wT[(w - 8) * 32 + j];
        }
        out[b * NW + w] = t * (1.f / 16777216.f);   // 2^-24
    }
}

extern "C" void kernel_launch(void* const* d_in, const int* in_sizes, int n_in,
                              void* d_out, int out_size)
{
    // Identify inputs by element count — robust to metadata ordering.
    const float* x = nullptr;      // 4096*256 = 1048576
    const float* W = nullptr;      // 12*256   = 3072
    const float* params = nullptr; // 4*12*1   = 48
    for (int i = 0; i < n_in; i++) {
        if      (in_sizes[i] == 4096 * 256) x      = (const float*)d_in[i];
        else if (in_sizes[i] == 12 * 256)   W      = (const float*)d_in[i];
        else if (in_sizes[i] == 48)         params = (const float*)d_in[i];
    }
    sim_kernel<<<4096, NT>>>(x, W, params, (float*)d_out);
}

// round 14
// speedup vs baseline: 3.8032x; 1.0556x over previous
#include <cuda_runtime.h>
#include <cstdint>

#define NW 12
#define DIM 4096       // 2^12
#define INDIM 256
#define NT 256

// Swizzle for 64-bit elements: conflict-free in all three exchange layouts
__device__ __forceinline__ int s2(int i) { return i ^ ((i >> 4) & 15); }

// ---- packed f32x2 ops (sm_103a) ----
__device__ __forceinline__ uint64_t addx2(uint64_t a, uint64_t b) {
    uint64_t r; asm("add.rn.f32x2 %0, %1, %2;" : "=l"(r) : "l"(a), "l"(b)); return r;
}
__device__ __forceinline__ uint64_t subx2(uint64_t a, uint64_t b) {
    uint64_t r; asm("sub.rn.f32x2 %0, %1, %2;" : "=l"(r) : "l"(a), "l"(b)); return r;
}
__device__ __forceinline__ uint64_t packx2(float lo, float hi) {
    uint64_t r; asm("mov.b64 %0, {%1, %2};" : "=l"(r) : "f"(lo), "f"(hi)); return r;
}
__device__ __forceinline__ void unpackx2(float& lo, float& hi, uint64_t v) {
    asm("mov.b64 {%0, %1}, %2;" : "=f"(lo), "=f"(hi) : "l"(v));
}

// In-register 4-level WHT butterflies on packed (cos,sin) pairs
__device__ __forceinline__ void wht16p(uint64_t U[16]) {
#pragma unroll
    for (int k = 0; k < 4; k++) {
        const int m = 1 << k;
#pragma unroll
        for (int i = 0; i < 16; i++) {
            if (!(i & m)) {
                uint64_t a = U[i], b = U[i | m];
                U[i]     = addx2(a, b);
                U[i | m] = subx2(a, b);
            }
        }
    }
}

__global__ void __launch_bounds__(NT, 5)
sim_kernel(const float* __restrict__ x, const float* __restrict__ W,
           const float* __restrict__ params, float* __restrict__ out)
{
    __shared__ __align__(16) uint64_t cs[DIM]; // 32 KB packed (cos,sin) WHT buffer
    __shared__ float red[NW * 32];             // angle partials (3-level reduced)
    __shared__ float cv[NW * 4];               // 48 Walsh coefficients
    __shared__ float wA[5 * 8];                // warp-WHT comps: wires 0..4 per warp
    __shared__ float w0[8];                    // warp totals of psum (wires 5..7)
    __shared__ float wT[4 * 32];               // T8..T11 partials

    const int tid  = threadIdx.x;
    const int b    = blockIdx.x;
    const int lane = tid & 31;
    const int warp = tid >> 5;

    // ---- angles[b,w] = dot(x[b,:], W[w,:]) ; 3 shfl levels + smem finish ----
    float xv = x[b * INDIM + tid];
#pragma unroll
    for (int w = 0; w < NW; w++) {
        float p = xv * __ldg(&W[w * INDIM + tid]);
        p += __shfl_xor_sync(0xffffffffu, p, 16);
        p += __shfl_xor_sync(0xffffffffu, p, 8);
        p += __shfl_xor_sync(0xffffffffu, p, 4);
        if (lane < 4) red[w * 32 + warp * 4 + lane] = p;
    }
    __syncthreads();

    // ---- 48 Walsh coefficients: RX(theta) on wire v with k CNOT-chains after it
    //      contributes -theta/2 at mask (P_k << v) & 0xFFF.
    if (tid < NW) {
        const int v = tid;
        float a = 0.f;
#pragma unroll
        for (int k = 0; k < 32; k++) a += red[v * 32 + k];
        cv[v * 4 + 0] = -0.5f * (a + params[v]);     // init + depth0 (P=0x111)
        cv[v * 4 + 1] = -0.5f * params[NW + v];      // depth1       (P=0x333)
        cv[v * 4 + 2] = -0.5f * params[2 * NW + v];  // depth2       (P=0x555)
        cv[v * 4 + 3] = -0.5f * params[3 * NW + v];  // depth3       (P=0xFFF)
    }
    __syncthreads();

    // ---- sparse phase evaluation: phi(y) = sum_t a_t (-1)^{<m_t, y>}
    // y = (tid<<4) | g. Bucket by mask low nibble (compile-time), sign from
    // parity(mask_hi & tid), then 4-level WHT over buckets gives phi for all g.
    uint64_t U[16];                 // packed (cos, sin)
    {
        float B[16];
#pragma unroll
        for (int n = 0; n < 16; n++) B[n] = 0.f;

        const int Pm[4] = {0x111, 0x333, 0x555, 0xFFF};
#pragma unroll
        for (int v = 0; v < NW; v++) {
#pragma unroll
            for (int i = 0; i < 4; i++) {
                const int m   = (Pm[i] << v) & 0xFFF;   // compile-time constant
                const int mhi = m >> 4, mlo = m & 15;
                float a = cv[v * 4 + i];                 // uniform LDS broadcast
                B[mlo] += (__popc(mhi & tid) & 1) ? -a : a;
            }
        }
        // WHT16 over B: level 0 scalar + pack pairs, levels 1-3 packed over j
        uint64_t C[8];
#pragma unroll
        for (int j = 0; j < 8; j++)
            C[j] = packx2(B[2 * j] + B[2 * j + 1], B[2 * j] - B[2 * j + 1]);
#pragma unroll
        for (int k = 0; k < 3; k++) {
            const int m = 1 << k;
#pragma unroll
            for (int j = 0; j < 8; j++) {
                if (!(j & m)) {
                    uint64_t a = C[j], bb = C[j | m];
                    C[j]     = addx2(a, bb);
                    C[j | m] = subx2(a, bb);
                }
            }
        }
        // phases -> packed unit vectors
#pragma unroll
        for (int j = 0; j < 8; j++) {
            float blo, bhi; unpackx2(blo, bhi, C[j]);
            float sv, cvv;
            __sincosf(blo, &sv, &cvv); U[2 * j]     = packx2(cvv, sv);
            __sincosf(bhi, &sv, &cvv); U[2 * j + 1] = packx2(cvv, sv);
        }
    }

    // ---- complex WHT of u = e^{i phi}: packed butterflies, LO -> MID -> HI ----
    wht16p(U);                                           // LO: y bits 3:0 local
#pragma unroll
    for (int g = 0; g < 16; g++) cs[s2((tid << 4) | g)] = U[g];
    __syncthreads();
    {   // MID: bits 7:4 local
        const int mb = ((tid >> 4) << 8) | (tid & 15);
#pragma unroll
        for (int g = 0; g < 16; g++) U[g] = cs[s2(mb | (g << 4))];
        wht16p(U);
#pragma unroll
        for (int g = 0; g < 16; g++) cs[s2(mb | (g << 4))] = U[g];
    }
    __syncthreads();
    // HI: m = (g<<8)|tid
#pragma unroll
    for (int g = 0; g < 16; g++) U[g] = cs[s2((g << 8) | tid)];
    wht16p(U);

    // ---- Parseval: <Z_w> = 2^-24 sum_m |U(m)|^2 (-1)^{m_w},  m=(g<<8)|tid.
    // psum/T8..T11 are 5 WHT components of P over g -> shared partial tree.
    float P[16];
#pragma unroll
    for (int g = 0; g < 16; g++) {
        float c, s; unpackx2(c, s, U[g]);
        P[g] = fmaf(c, c, s * s);
    }
    float sj[8], dj[8];
#pragma unroll
    for (int j = 0; j < 8; j++) {
        sj[j] = P[2 * j] + P[2 * j + 1];
        dj[j] = P[2 * j] - P[2 * j + 1];
    }
    float T8  = ((dj[0] + dj[1]) + (dj[2] + dj[3])) + ((dj[4] + dj[5]) + (dj[6] + dj[7]));
    float u0 = sj[0] + sj[1], u1 = sj[2] + sj[3], u2 = sj[4] + sj[5], u3 = sj[6] + sj[7];
    float v0 = sj[0] - sj[1], v1 = sj[2] - sj[3], v2 = sj[4] - sj[5], v3 = sj[6] - sj[7];
    float T9  = (v0 + v1) + (v2 + v3);
    float p0 = u0 + u1, p1 = u2 + u3;
    float T10 = (u0 - u1) + (u2 - u3);
    float psum = p0 + p1;
    float T11  = p0 - p1;

    // Warp-WHT on psum: lane L ends with sum_t (-1)^{<L,t>} psum_t over the warp.
    {
        float v = psum;
#pragma unroll
        for (int o = 1; o < 32; o <<= 1) {
            float r = __shfl_xor_sync(0xffffffffu, v, o);
            v = (lane & o) ? (r - v) : (v + r);
        }
        if (lane == 0) w0[warp] = v;                       // component 0 (warp total)
        else if ((lane & (lane - 1)) == 0)                 // lanes 1,2,4,8,16
            wA[__popc(lane - 1) * 8 + warp] = v;           // wire = log2(lane)
    }
    // T8..T11: 3 shfl levels, lanes 0..3 store the 4 group sums
    {
#pragma unroll
        for (int o = 16; o >= 4; o >>= 1) {
            T8  += __shfl_xor_sync(0xffffffffu, T8,  o);
            T9  += __shfl_xor_sync(0xffffffffu, T9,  o);
            T10 += __shfl_xor_sync(0xffffffffu, T10, o);
            T11 += __shfl_xor_sync(0xffffffffu, T11, o);
        }
        if (lane < 4) {
            wT[0 * 32 + warp * 4 + lane] = T8;
            wT[1 * 32 + warp * 4 + lane] = T9;
            wT[2 * 32 + warp * 4 + lane] = T10;
            wT[3 * 32 + warp * 4 + lane] = T11;
        }
    }
    __syncthreads();

    if (tid < NW) {
        float t = 0.f;
        const int w = tid;
        if (w < 5) {                       // tid bit w = lane bit w
#pragma unroll
            for (int k = 0; k < 8; k++) t += wA[w * 8 + k];
        } else if (w < 8) {                // tid bit w = warp bit (w-5)
#pragma unroll
            for (int k = 0; k < 8; k++)
                t += ((k >> (w - 5)) & 1) ? -w0[k] : w0[k];
        } else {                           // wires 8..11 from T partials
#pragma unroll
            for (int j = 0; j < 32; j++) t += wT[(w - 8) * 32 + j];
        }
        out[b * NW + w] = t * (1.f / 16777216.f);   // 2^-24
    }
}

extern "C" void kernel_launch(void* const* d_in, const int* in_sizes, int n_in,
                              void* d_out, int out_size)
{
    // Identify inputs by element count — robust to metadata ordering.
    const float* x = nullptr;      // 4096*256 = 1048576
    const float* W = nullptr;      // 12*256   = 3072
    const float* params = nullptr; // 4*12*1   = 48
    for (int i = 0; i < n_in; i++) {
        if      (in_sizes[i] == 4096 * 256) x      = (const float*)d_in[i];
        else if (in_sizes[i] == 12 * 256)   W      = (const float*)d_in[i];
        else if (in_sizes[i] == 48)         params = (const float*)d_in[i];
    }
    sim_kernel<<<4096, NT>>>(x, W, params, (float*)d_out);
}

// round 15
// speedup vs baseline: 4.0008x; 1.0519x over previous
#include <cuda_runtime.h>
#include <cstdint>

#define NW 12
#define DIM 4096       // 2^12
#define INDIM 256
#define NT 256

// Swizzle for 64-bit elements: conflict-free in all three exchange layouts
__device__ __forceinline__ int s2(int i) { return i ^ ((i >> 4) & 15); }

// ---- packed f32x2 ops (sm_103a) ----
__device__ __forceinline__ uint64_t addx2(uint64_t a, uint64_t b) {
    uint64_t r; asm("add.rn.f32x2 %0, %1, %2;" : "=l"(r) : "l"(a), "l"(b)); return r;
}
__device__ __forceinline__ uint64_t subx2(uint64_t a, uint64_t b) {
    uint64_t r; asm("sub.rn.f32x2 %0, %1, %2;" : "=l"(r) : "l"(a), "l"(b)); return r;
}
__device__ __forceinline__ uint64_t packx2(float lo, float hi) {
    uint64_t r; asm("mov.b64 %0, {%1, %2};" : "=l"(r) : "f"(lo), "f"(hi)); return r;
}
__device__ __forceinline__ void unpackx2(float& lo, float& hi, uint64_t v) {
    asm("mov.b64 {%0, %1}, %2;" : "=f"(lo), "=f"(hi) : "l"(v));
}

// In-register 4-level WHT butterflies on packed (cos,sin) pairs
__device__ __forceinline__ void wht16p(uint64_t U[16]) {
#pragma unroll
    for (int k = 0; k < 4; k++) {
        const int m = 1 << k;
#pragma unroll
        for (int i = 0; i < 16; i++) {
            if (!(i & m)) {
                uint64_t a = U[i], b = U[i | m];
                U[i]     = addx2(a, b);
                U[i | m] = subx2(a, b);
            }
        }
    }
}

__global__ void __launch_bounds__(NT, 5)
sim_kernel(const float* __restrict__ x, const float* __restrict__ W,
           const float* __restrict__ params, float* __restrict__ out)
{
    __shared__ __align__(16) uint64_t cs[DIM]; // 32 KB packed (cos,sin) WHT buffer
    __shared__ float red[NW * 2];              // per-wire 2 warp partials
    __shared__ float cv[44];                   // 43 merged Walsh coefficients
    __shared__ float wA[5 * 8];                // warp-WHT comps: wires 0..4 per warp
    __shared__ float w0[8];                    // warp totals of psum (wires 5..7)
    __shared__ float wT[4 * 32];               // T8..T11 partials

    const int tid  = threadIdx.x;
    const int b    = blockIdx.x;
    const int lane = tid & 31;
    const int warp = tid >> 5;

    // ---- angles: vectorized dot. 64 threads per wire, float4 chunks.
    // thread's x chunk is identical across the 3 iterations -> load once.
    const float4 xv4 = __ldg(reinterpret_cast<const float4*>(x + b * INDIM) + (tid & 63));
    const int grp = tid >> 6;     // 0..3
#pragma unroll
    for (int it = 0; it < 3; it++) {
        const int w = it * 4 + grp;
        float4 wv = __ldg(reinterpret_cast<const float4*>(W + w * INDIM) + (tid & 63));
        float p = fmaf(xv4.x, wv.x, fmaf(xv4.y, wv.y, fmaf(xv4.z, wv.z, xv4.w * wv.w)));
        p += __shfl_xor_sync(0xffffffffu, p, 16);
        p += __shfl_xor_sync(0xffffffffu, p, 8);
        p += __shfl_xor_sync(0xffffffffu, p, 4);
        p += __shfl_xor_sync(0xffffffffu, p, 2);
        p += __shfl_xor_sync(0xffffffffu, p, 1);
        if (lane == 0) red[w * 2 + (warp & 1)] = p;
    }
    __syncthreads();

    // ---- merged Walsh coefficients. RX(theta) on wire v with k CNOT-chains after
    // it lands at mask (P_k << v) & 0xFFF. v=11: all four masks = 0x800 (merge 4->1);
    // v=10: masks pair up (0x400: P 0x111/0x555, 0xC00: P 0x333/0xFFF).
    if (tid < NW) {
        const int v = tid;
        float a = red[v * 2] + red[v * 2 + 1];
        if (v <= 9) {
            cv[v * 4 + 0] = -0.5f * (a + params[v]);      // P=0x111 (init+depth0)
            cv[v * 4 + 1] = -0.5f * params[NW + v];       // P=0x333
            cv[v * 4 + 2] = -0.5f * params[2 * NW + v];   // P=0x555
            cv[v * 4 + 3] = -0.5f * params[3 * NW + v];   // P=0xFFF
        } else if (v == 10) {
            cv[40] = -0.5f * (a + params[10] + params[2 * NW + 10]);      // mask 0x400
            cv[41] = -0.5f * (params[NW + 10] + params[3 * NW + 10]);     // mask 0xC00
        } else {
            cv[42] = -0.5f * (a + params[11] + params[NW + 11]
                              + params[2 * NW + 11] + params[3 * NW + 11]); // mask 0x800
        }
    }
    __syncthreads();

    // ---- sparse phase evaluation: phi(y) = sum_t a_t (-1)^{<m_t, y>}
    // y = (tid<<4) | g. Bucket by mask low nibble (compile-time), sign from
    // parity(mask_hi & tid), then 4-level WHT over buckets gives phi for all g.
    uint64_t U[16];                 // packed (cos, sin)
    {
        float B[16];
#pragma unroll
        for (int n = 0; n < 16; n++) B[n] = 0.f;

        const int Pm[4] = {0x111, 0x333, 0x555, 0xFFF};
#pragma unroll
        for (int v = 0; v < 10; v++) {
#pragma unroll
            for (int i = 0; i < 4; i++) {
                const int m   = (Pm[i] << v) & 0xFFF;   // compile-time constant
                const int mhi = m >> 4, mlo = m & 15;
                float a = cv[v * 4 + i];                 // uniform LDS broadcast
                B[mlo] += (__popc(mhi & tid) & 1) ? -a : a;
            }
        }
        {   // merged high-wire terms, all land in bucket 0; signs are tid-bit parities
            float a = cv[40]; B[0] += ((tid >> 6) & 1) ? -a : a;                 // mhi 0x40
            a = cv[41]; B[0] += (((tid >> 6) ^ (tid >> 7)) & 1) ? -a : a;        // mhi 0xC0
            a = cv[42]; B[0] += ((tid >> 7) & 1) ? -a : a;                       // mhi 0x80
        }
        // WHT16 over B: level 0 scalar + pack pairs, levels 1-3 packed over j
        uint64_t C[8];
#pragma unroll
        for (int j = 0; j < 8; j++)
            C[j] = packx2(B[2 * j] + B[2 * j + 1], B[2 * j] - B[2 * j + 1]);
#pragma unroll
        for (int k = 0; k < 3; k++) {
            const int m = 1 << k;
#pragma unroll
            for (int j = 0; j < 8; j++) {
                if (!(j & m)) {
                    uint64_t a = C[j], bb = C[j | m];
                    C[j]     = addx2(a, bb);
                    C[j | m] = subx2(a, bb);
                }
            }
        }
        // phases -> packed unit vectors
#pragma unroll
        for (int j = 0; j < 8; j++) {
            float blo, bhi; unpackx2(blo, bhi, C[j]);
            float sv, cvv;
            __sincosf(blo, &sv, &cvv); U[2 * j]     = packx2(cvv, sv);
            __sincosf(bhi, &sv, &cvv); U[2 * j + 1] = packx2(cvv, sv);
        }
    }

    // ---- complex WHT of u = e^{i phi}: packed butterflies, LO -> MID -> HI ----
    wht16p(U);                                           // LO: y bits 3:0 local
#pragma unroll
    for (int g = 0; g < 16; g++) cs[s2((tid << 4) | g)] = U[g];
    __syncthreads();
    {   // MID: bits 7:4 local
        const int mb = ((tid >> 4) << 8) | (tid & 15);
#pragma unroll
        for (int g = 0; g < 16; g++) U[g] = cs[s2(mb | (g << 4))];
        wht16p(U);
#pragma unroll
        for (int g = 0; g < 16; g++) cs[s2(mb | (g << 4))] = U[g];
    }
    __syncthreads();
    // HI: m = (g<<8)|tid
#pragma unroll
    for (int g = 0; g < 16; g++) U[g] = cs[s2((g << 8) | tid)];
    wht16p(U);

    // ---- Parseval: <Z_w> = 2^-24 sum_m |U(m)|^2 (-1)^{m_w},  m=(g<<8)|tid.
    // psum/T8..T11 are 5 WHT components of P over g -> shared partial tree.
    float P[16];
#pragma unroll
    for (int g = 0; g < 16; g++) {
        float c, s; unpackx2(c, s, U[g]);
        P[g] = fmaf(c, c, s * s);
    }
    float sj[8], dj[8];
#pragma unroll
    for (int j = 0; j < 8; j++) {
        sj[j] = P[2 * j] + P[2 * j + 1];
        dj[j] = P[2 * j] - P[2 * j + 1];
    }
    float T8  = ((dj[0] + dj[1]) + (dj[2] + dj[3])) + ((dj[4] + dj[5]) + (dj[6] + dj[7]));
    float u0 = sj[0] + sj[1], u1 = sj[2] + sj[3], u2 = sj[4] + sj[5], u3 = sj[6] + sj[7];
    float v0 = sj[0] - sj[1], v1 = sj[2] - sj[3], v2 = sj[4] - sj[5], v3 = sj[6] - sj[7];
    float T9  = (v0 + v1) + (v2 + v3);
    float p0 = u0 + u1, p1 = u2 + u3;
    float T10 = (u0 - u1) + (u2 - u3);
    float psum = p0 + p1;
    float T11  = p0 - p1;

    // Warp-WHT on psum: lane L ends with sum_t (-1)^{<L,t>} psum_t over the warp.
    {
        float v = psum;
#pragma unroll
        for (int o = 1; o < 32; o <<= 1) {
            float r = __shfl_xor_sync(0xffffffffu, v, o);
            v = (lane & o) ? (r - v) : (v + r);
        }
        if (lane == 0) w0[warp] = v;                       // component 0 (warp total)
        else if ((lane & (lane - 1)) == 0)                 // lanes 1,2,4,8,16
            wA[__popc(lane - 1) * 8 + warp] = v;           // wire = log2(lane)
    }
    // T8..T11: 3 shfl levels, lanes 0..3 store the 4 group sums
    {
#pragma unroll
        for (int o = 16; o >= 4; o >>= 1) {
            T8  += __shfl_xor_sync(0xffffffffu, T8,  o);
            T9  += __shfl_xor_sync(0xffffffffu, T9,  o);
            T10 += __shfl_xor_sync(0xffffffffu, T10, o);
            T11 += __shfl_xor_sync(0xffffffffu, T11, o);
        }
        if (lane < 4) {
            wT[0 * 32 + warp * 4 + lane] = T8;
            wT[1 * 32 + warp * 4 + lane] = T9;
            wT[2 * 32 + warp * 4 + lane] = T10;
            wT[3 * 32 + warp * 4 + lane] = T11;
        }
    }
    __syncthreads();

    if (tid < NW) {
        float t = 0.f;
        const int w = tid;
        if (w < 5) {                       // tid bit w = lane bit w
#pragma unroll
            for (int k = 0; k < 8; k++) t += wA[w * 8 + k];
        } else if (w < 8) {                // tid bit w = warp bit (w-5)
#pragma unroll
            for (int k = 0; k < 8; k++)
                t += ((k >> (w - 5)) & 1) ? -w0[k] : w0[k];
        } else {                           // wires 8..11 from T partials
#pragma unroll
            for (int j = 0; j < 32; j++) t += wT[(w - 8) * 32 + j];
        }
        out[b * NW + w] = t * (1.f / 16777216.f);   // 2^-24
    }
}

extern "C" void kernel_launch(void* const* d_in, const int* in_sizes, int n_in,
                              void* d_out, int out_size)
{
    // Identify inputs by element count — robust to metadata ordering.
    const float* x = nullptr;      // 4096*256 = 1048576
    const float* W = nullptr;      // 12*256   = 3072
    const float* params = nullptr; // 4*12*1   = 48
    for (int i = 0; i < n_in; i++) {
        if      (in_sizes[i] == 4096 * 256) x      = (const float*)d_in[i];
        else if (in_sizes[i] == 12 * 256)   W      = (const float*)d_in[i];
        else if (in_sizes[i] == 48)         params = (const float*)d_in[i];
    }
    sim_kernel<<<4096, NT>>>(x, W, params, (float*)d_out);
}

// round 16
// speedup vs baseline: 4.2273x; 1.0566x over previous
#include <cuda_runtime.h>
#include <cstdint>

#define NW 12
#define DIM 4096       // 2^12
#define INDIM 256
#define NT 256

// ---- packed f32x2 ops (sm_103a) ----
__device__ __forceinline__ uint64_t addx2(uint64_t a, uint64_t b) {
    uint64_t r; asm("add.rn.f32x2 %0, %1, %2;" : "=l"(r) : "l"(a), "l"(b)); return r;
}
__device__ __forceinline__ uint64_t subx2(uint64_t a, uint64_t b) {
    uint64_t r; asm("sub.rn.f32x2 %0, %1, %2;" : "=l"(r) : "l"(a), "l"(b)); return r;
}
__device__ __forceinline__ uint64_t mulx2(uint64_t a, uint64_t b) {
    uint64_t r; asm("mul.rn.f32x2 %0, %1, %2;" : "=l"(r) : "l"(a), "l"(b)); return r;
}
__device__ __forceinline__ uint64_t packx2(float lo, float hi) {
    uint64_t r; asm("mov.b64 %0, {%1, %2};" : "=l"(r) : "f"(lo), "f"(hi)); return r;
}
__device__ __forceinline__ void unpackx2(float& lo, float& hi, uint64_t v) {
    asm("mov.b64 {%0, %1}, %2;" : "=f"(lo), "=f"(hi) : "l"(v));
}
__device__ __forceinline__ float hsum(uint64_t v) {
    float lo, hi; unpackx2(lo, hi, v); return lo + hi;
}

// In-register 4-level WHT butterflies on packed (cos,sin) pairs
__device__ __forceinline__ void wht16p(uint64_t U[16]) {
#pragma unroll
    for (int k = 0; k < 4; k++) {
        const int m = 1 << k;
#pragma unroll
        for (int i = 0; i < 16; i++) {
            if (!(i & m)) {
                uint64_t a = U[i], b = U[i | m];
                U[i]     = addx2(a, b);
                U[i | m] = subx2(a, b);
            }
        }
    }
}

__global__ void __launch_bounds__(NT, 5)
sim_kernel(const float* __restrict__ x, const float* __restrict__ W,
           const float* __restrict__ params, float* __restrict__ out)
{
    __shared__ __align__(16) uint64_t cs[DIM]; // 32 KB packed (cos,sin) WHT buffer
    __shared__ float red[NW * 2];              // per-wire 2 warp partials
    __shared__ float cv[44];                   // 43 merged Walsh coefficients
    __shared__ float wA[5 * 8];                // warp-WHT comps: wires 0..4 per warp
    __shared__ float w0[8];                    // warp totals of psum (wires 5..7)
    __shared__ float wT[4 * 32];               // T8..T11 partials

    const int tid  = threadIdx.x;
    const int b    = blockIdx.x;
    const int lane = tid & 31;
    const int warp = tid >> 5;

    // Closed-form swizzle bases (algebraic reduction of i ^ ((i>>4)&15)):
    //   LO : idx = baseLO ^ g         baseLO = (tid<<4) | (tid&15)
    //   MID: idx = baseMID ^ (17*g)   baseMID = ((tid>>4)<<8) | (tid&15)
    //   HI : idx = baseHI  + (g<<8)   baseHI  = tid ^ ((tid>>4)&15)   (immediates!)
    const int baseLO  = (tid << 4) | (tid & 15);
    const int baseMID = ((tid >> 4) << 8) | (tid & 15);
    const int baseHI  = tid ^ ((tid >> 4) & 15);

    // ---- angles: vectorized dot. 64 threads per wire, float4 chunks. ----
    const float4 xv4 = __ldg(reinterpret_cast<const float4*>(x + b * INDIM) + (tid & 63));
    const int grp = tid >> 6;     // 0..3
#pragma unroll
    for (int it = 0; it < 3; it++) {
        const int w = it * 4 + grp;
        float4 wv = __ldg(reinterpret_cast<const float4*>(W + w * INDIM) + (tid & 63));
        float p = fmaf(xv4.x, wv.x, fmaf(xv4.y, wv.y, fmaf(xv4.z, wv.z, xv4.w * wv.w)));
        p += __shfl_xor_sync(0xffffffffu, p, 16);
        p += __shfl_xor_sync(0xffffffffu, p, 8);
        p += __shfl_xor_sync(0xffffffffu, p, 4);
        p += __shfl_xor_sync(0xffffffffu, p, 2);
        p += __shfl_xor_sync(0xffffffffu, p, 1);
        if (lane == 0) red[w * 2 + (warp & 1)] = p;
    }
    __syncthreads();

    // ---- merged Walsh coefficients (43 distinct masks) ----
    if (tid < NW) {
        const int v = tid;
        float a = red[v * 2] + red[v * 2 + 1];
        if (v <= 9) {
            cv[v * 4 + 0] = -0.5f * (a + params[v]);      // P=0x111 (init+depth0)
            cv[v * 4 + 1] = -0.5f * params[NW + v];       // P=0x333
            cv[v * 4 + 2] = -0.5f * params[2 * NW + v];   // P=0x555
            cv[v * 4 + 3] = -0.5f * params[3 * NW + v];   // P=0xFFF
        } else if (v == 10) {
            cv[40] = -0.5f * (a + params[10] + params[2 * NW + 10]);      // mask 0x400
            cv[41] = -0.5f * (params[NW + 10] + params[3 * NW + 10]);     // mask 0xC00
        } else {
            cv[42] = -0.5f * (a + params[11] + params[NW + 11]
                              + params[2 * NW + 11] + params[3 * NW + 11]); // mask 0x800
        }
    }
    __syncthreads();

    // ---- sparse phase evaluation: phi(y) = sum_t a_t (-1)^{<m_t, y>}
    // y = (tid<<4) | g. Signs precomputed as bit-words: for pattern P at shift v,
    // parity(mask & y_hi-part) = bit v of w_P, with T = tid<<4:
    //   w1 = T^(T>>4)^(T>>8); w3 = w1^(w1>>1); w5 = w1^(w1>>2); wF = w3^(w3>>2)
    uint64_t U[16];                 // packed (cos, sin)
    {
        const uint32_t T12 = (uint32_t)tid << 4;
        const uint32_t w1v = T12 ^ (T12 >> 4) ^ (T12 >> 8);
        const uint32_t w3v = w1v ^ (w1v >> 1);
        const uint32_t w5v = w1v ^ (w1v >> 2);
        const uint32_t wFv = w3v ^ (w3v >> 2);
        const uint32_t wArr[4] = {w1v, w3v, w5v, wFv};

        float B[16];
#pragma unroll
        for (int n = 0; n < 16; n++) B[n] = 0.f;

        const int Pm[4] = {0x111, 0x333, 0x555, 0xFFF};
#pragma unroll
        for (int v = 0; v < 10; v++) {
#pragma unroll
            for (int i = 0; i < 4; i++) {
                const int m   = (Pm[i] << v) & 0xFFF;   // compile-time constant
                const int mlo = m & 15;
                float a = cv[v * 4 + i];                 // uniform LDS broadcast
                uint32_t sgn = (wArr[i] << (31 - v)) & 0x80000000u;
                B[mlo] += __int_as_float(__float_as_int(a) ^ sgn);
            }
        }
        {   // merged high-wire terms -> bucket 0; signs from tid bits 6/7
            const uint32_t u = (uint32_t)tid ^ ((uint32_t)tid >> 1);
            float a = cv[40];
            B[0] += __int_as_float(__float_as_int(a) ^ (((uint32_t)tid << 25) & 0x80000000u));
            a = cv[41];
            B[0] += __int_as_float(__float_as_int(a) ^ ((u << 25) & 0x80000000u));
            a = cv[42];
            B[0] += __int_as_float(__float_as_int(a) ^ (((uint32_t)tid << 24) & 0x80000000u));
        }
        // WHT16 over B: level 0 scalar + pack pairs, levels 1-3 packed over j
        uint64_t C[8];
#pragma unroll
        for (int j = 0; j < 8; j++)
            C[j] = packx2(B[2 * j] + B[2 * j + 1], B[2 * j] - B[2 * j + 1]);
#pragma unroll
        for (int k = 0; k < 3; k++) {
            const int m = 1 << k;
#pragma unroll
            for (int j = 0; j < 8; j++) {
                if (!(j & m)) {
                    uint64_t a = C[j], bb = C[j | m];
                    C[j]     = addx2(a, bb);
                    C[j | m] = subx2(a, bb);
                }
            }
        }
        // phases -> packed unit vectors
#pragma unroll
        for (int j = 0; j < 8; j++) {
            float blo, bhi; unpackx2(blo, bhi, C[j]);
            float sv, cvv;
            __sincosf(blo, &sv, &cvv); U[2 * j]     = packx2(cvv, sv);
            __sincosf(bhi, &sv, &cvv); U[2 * j + 1] = packx2(cvv, sv);
        }
    }

    // ---- complex WHT of u = e^{i phi}: packed butterflies, LO -> MID -> HI ----
    wht16p(U);                                           // LO: y bits 3:0 local
#pragma unroll
    for (int g = 0; g < 16; g++) cs[baseLO ^ g] = U[g];
    __syncthreads();
    {   // MID: bits 7:4 local
#pragma unroll
        for (int g = 0; g < 16; g++) U[g] = cs[baseMID ^ (17 * g)];
        wht16p(U);
#pragma unroll
        for (int g = 0; g < 16; g++) cs[baseMID ^ (17 * g)] = U[g];
    }
    __syncthreads();
    // HI: m = (g<<8)|tid  -> pure immediate offsets
#pragma unroll
    for (int g = 0; g < 16; g++) U[g] = cs[baseHI + (g << 8)];
    wht16p(U);

    // ---- Parseval, packed tree: <Z_w> = 2^-24 sum_m |U(m)|^2 (-1)^{m_w} ----
    uint64_t Q[16];
#pragma unroll
    for (int g = 0; g < 16; g++) Q[g] = mulx2(U[g], U[g]);   // (c^2, s^2)
    uint64_t sj[8], dj[8];
#pragma unroll
    for (int j = 0; j < 8; j++) {
        sj[j] = addx2(Q[2 * j], Q[2 * j + 1]);
        dj[j] = subx2(Q[2 * j], Q[2 * j + 1]);
    }
    uint64_t T8p = addx2(addx2(addx2(dj[0], dj[1]), addx2(dj[2], dj[3])),
                         addx2(addx2(dj[4], dj[5]), addx2(dj[6], dj[7])));
    uint64_t u0 = addx2(sj[0], sj[1]), u1 = addx2(sj[2], sj[3]);
    uint64_t u2 = addx2(sj[4], sj[5]), u3 = addx2(sj[6], sj[7]);
    uint64_t v0 = subx2(sj[0], sj[1]), v1 = subx2(sj[2], sj[3]);
    uint64_t v2 = subx2(sj[4], sj[5]), v3 = subx2(sj[6], sj[7]);
    uint64_t T9p  = addx2(addx2(v0, v1), addx2(v2, v3));
    uint64_t p0 = addx2(u0, u1), p1 = addx2(u2, u3);
    uint64_t T10p = addx2(subx2(u0, u1), subx2(u2, u3));
    float psum = hsum(addx2(p0, p1));
    float T11  = hsum(subx2(p0, p1));
    float T8   = hsum(T8p);
    float T9   = hsum(T9p);
    float T10  = hsum(T10p);

    // Warp-WHT on psum: lane L ends with sum_t (-1)^{<L,t>} psum_t over the warp.
    {
        float v = psum;
#pragma unroll
        for (int o = 1; o < 32; o <<= 1) {
            float r = __shfl_xor_sync(0xffffffffu, v, o);
            v = (lane & o) ? (r - v) : (v + r);
        }
        if (lane == 0) w0[warp] = v;                       // component 0 (warp total)
        else if ((lane & (lane - 1)) == 0)                 // lanes 1,2,4,8,16
            wA[__popc(lane - 1) * 8 + warp] = v;           // wire = log2(lane)
    }
    // T8..T11: 3 shfl levels, lanes 0..3 store the 4 group sums
    {
#pragma unroll
        for (int o = 16; o >= 4; o >>= 1) {
            T8  += __shfl_xor_sync(0xffffffffu, T8,  o);
            T9  += __shfl_xor_sync(0xffffffffu, T9,  o);
            T10 += __shfl_xor_sync(0xffffffffu, T10, o);
            T11 += __shfl_xor_sync(0xffffffffu, T11, o);
        }
        if (lane < 4) {
            wT[0 * 32 + warp * 4 + lane] = T8;
            wT[1 * 32 + warp * 4 + lane] = T9;
            wT[2 * 32 + warp * 4 + lane] = T10;
            wT[3 * 32 + warp * 4 + lane] = T11;
        }
    }
    __syncthreads();

    if (tid < NW) {
        float t = 0.f;
        const int w = tid;
        if (w < 5) {                       // tid bit w = lane bit w
#pragma unroll
            for (int k = 0; k < 8; k++) t += wA[w * 8 + k];
        } else if (w < 8) {                // tid bit w = warp bit (w-5)
#pragma unroll
            for (int k = 0; k < 8; k++)
                t += ((k >> (w - 5)) & 1) ? -w0[k] : w0[k];
        } else {                           // wires 8..11 from T partials
#pragma unroll
            for (int j = 0; j < 32; j++) t += wT[(w - 8) * 32 + j];
        }
        out[b * NW + w] = t * (1.f / 16777216.f);   // 2^-24
    }
}

extern "C" void kernel_launch(void* const* d_in, const int* in_sizes, int n_in,
                              void* d_out, int out_size)
{
    // Identify inputs by element count — robust to metadata ordering.
    const float* x = nullptr;      // 4096*256 = 1048576
    const float* W = nullptr;      // 12*256   = 3072
    const float* params = nullptr; // 4*12*1   = 48
    for (int i = 0; i < n_in; i++) {
        if      (in_sizes[i] == 4096 * 256) x      = (const float*)d_in[i];
        else if (in_sizes[i] == 12 * 256)   W      = (const float*)d_in[i];
        else if (in_sizes[i] == 48)         params = (const float*)d_in[i];
    }
    sim_kernel<<<4096, NT>>>(x, W, params, (float*)d_out);
}